// round 15
// baseline (speedup 1.0000x reference)
#include <cuda_runtime.h>
#include <cuda_bf16.h>
#include <math.h>
#include <cstdint>

#define N_NODES 10000
#define N_EDGES 50000
#define IN_F    1433
#define OUT_F   256
#define K_PAD   1440              // 45 * 32
#define NCHUNK  45                // K chunks of 32

// ---------------- device scratch (no allocations allowed) ----------------
__device__ __nv_bfloat16 g_a_hi[(size_t)N_NODES * K_PAD];
__device__ __nv_bfloat16 g_a_lo[(size_t)N_NODES * K_PAD];
__device__ __nv_bfloat16 g_w_hi[(size_t)K_PAD * OUT_F];   // [k][n]
__device__ __nv_bfloat16 g_w_lo[(size_t)K_PAD * OUT_F];
__device__ int g_count[N_NODES];
__device__ int g_start[N_NODES + 1];   // after fill: bucket END per node
__device__ int g_src[N_EDGES];
__device__ int g_edges_is32;
__device__ int g_ticket1;              // zero-init; self-resetting
__device__ int g_ticket2;
__device__ int g_flag;

// ---------------- helpers ----------------
__device__ __forceinline__ uint32_t smem_u32(const void* p) {
    uint32_t a;
    asm("{ .reg .u64 t; cvta.to.shared.u64 t, %1; cvt.u32.u64 %0, t; }" : "=r"(a) : "l"(p));
    return a;
}
__device__ __forceinline__ void cp16(uint32_t dst, const void* src, uint32_t bytes) {
    asm volatile("cp.async.cg.shared.global [%0], [%1], 16, %2;"
                 :: "r"(dst), "l"(src), "r"(bytes) : "memory");
}
__device__ __forceinline__ void cp_commit() {
    asm volatile("cp.async.commit_group;" ::: "memory");
}
template <int N>
__device__ __forceinline__ void cp_wait() {
    asm volatile("cp.async.wait_group %0;" :: "n"(N) : "memory");
}
__device__ __forceinline__ void ldsm_x4(uint32_t (&r)[4], uint32_t addr) {
    asm volatile("ldmatrix.sync.aligned.m8n8.x4.shared.b16 {%0,%1,%2,%3}, [%4];"
                 : "=r"(r[0]), "=r"(r[1]), "=r"(r[2]), "=r"(r[3]) : "r"(addr));
}
__device__ __forceinline__ void ldsm_x4_t(uint32_t (&r)[4], uint32_t addr) {
    asm volatile("ldmatrix.sync.aligned.m8n8.x4.trans.shared.b16 {%0,%1,%2,%3}, [%4];"
                 : "=r"(r[0]), "=r"(r[1]), "=r"(r[2]), "=r"(r[3]) : "r"(addr));
}
__device__ __forceinline__ void mma_bf16(float (&d)[4], const uint32_t (&a)[4],
                                         uint32_t b0, uint32_t b1) {
    asm volatile(
        "mma.sync.aligned.m16n8k16.row.col.f32.bf16.bf16.f32 "
        "{%0,%1,%2,%3}, {%4,%5,%6,%7}, {%8,%9}, {%0,%1,%2,%3};"
        : "+f"(d[0]), "+f"(d[1]), "+f"(d[2]), "+f"(d[3])
        : "r"(a[0]), "r"(a[1]), "r"(a[2]), "r"(a[3]), "r"(b0), "r"(b1));
}

// swizzles (byte offsets, tile-base-relative)
__device__ __forceinline__ uint32_t sw128(uint32_t off) { return off ^ ((off >> 3) & 0x70); }
__device__ __forceinline__ uint32_t sw64(uint32_t off)  { return off ^ ((off >> 3) & 0x30); }

// ---------------- 1) init: zero histogram + detect edge dtype ----------------
__global__ void __launch_bounds__(256) k_init(const void* __restrict__ edges) {
    int i = blockIdx.x * blockDim.x + threadIdx.x;
    if (i < N_NODES) g_count[i] = 0;
    if (blockIdx.x == 0 && threadIdx.x < 32) {
        const long long* e64 = (const long long*)edges;
        int lane = threadIdx.x;
        int bad = 0;
#pragma unroll
        for (int j = 0; j < 2; j++) {
            int p = lane * 2 + j;
            long long d = e64[2 * p], s = e64[2 * p + 1];
            if (d < 0 || d > N_NODES || s < 0 || s > N_NODES) bad = 1;
        }
        unsigned m = __ballot_sync(0xFFFFFFFFu, bad);
        if (lane == 0) g_edges_is32 = (m != 0) ? 1 : 0;
    }
}

__device__ __forceinline__ void load_edge(const void* edges, int e,
                                          long long& dst, long long& src) {
    if (g_edges_is32) {
        const int* p = (const int*)edges;
        dst = p[2 * e]; src = p[2 * e + 1];
    } else {
        const long long* p = (const long long*)edges;
        dst = p[2 * e]; src = p[2 * e + 1];
    }
}

// ---------------- 2) fused hist + scan + fill (49 co-resident blocks) ----------------
#define EDGE_GRID ((N_EDGES + 1023) / 1024)

__global__ void __launch_bounds__(1024) k_edges(const void* __restrict__ edges) {
    int e = blockIdx.x * 1024 + threadIdx.x;
    long long dst = -1, src = -1;
    bool valid = false;
    if (e < N_EDGES) {
        load_edge(edges, e, dst, src);
        valid = (src >= 0 && src < N_NODES && dst >= 0 && dst < N_NODES);
        if (valid) atomicAdd(&g_count[(int)dst], 1);
    }

    __shared__ int lastFlag;
    __syncthreads();
    if (threadIdx.x == 0) {
        __threadfence();
        lastFlag = (atomicAdd(&g_ticket1, 1) == (int)gridDim.x - 1);
    }
    __syncthreads();

    if (lastFlag) {
        __threadfence();
        // ---- exclusive scan over g_count (1024 threads, 10 bins each) ----
        __shared__ int wsum[32];
        const int CH = 10;
        int t = threadIdx.x;
        int lane = t & 31, w = t >> 5;
        int base = t * CH;
        int s = 0;
        int cnt[CH];
#pragma unroll
        for (int i = 0; i < CH; i++) {
            int idx = base + i;
            cnt[i] = (idx < N_NODES) ? g_count[idx] : 0;
            s += cnt[i];
        }
        int v = s;
#pragma unroll
        for (int off = 1; off < 32; off <<= 1) {
            int u = __shfl_up_sync(0xFFFFFFFFu, v, off);
            if (lane >= off) v += u;
        }
        if (lane == 31) wsum[w] = v;
        __syncthreads();
        if (w == 0) {
            int x = wsum[lane];
#pragma unroll
            for (int off = 1; off < 32; off <<= 1) {
                int u = __shfl_up_sync(0xFFFFFFFFu, x, off);
                if (lane >= off) x += u;
            }
            wsum[lane] = x;
        }
        __syncthreads();
        int run = ((w > 0) ? wsum[w - 1] : 0) + (v - s);
#pragma unroll
        for (int i = 0; i < CH; i++) {
            int idx = base + i;
            if (idx < N_NODES) {
                g_start[idx] = run;       // bucket start (fill turns it into end)
                run += cnt[i];
            }
        }
        if (t == 1023) g_start[N_NODES] = run;
        __syncthreads();
        if (t == 0) {
            g_ticket1 = 0;                // safe: all blocks already ticketed
            __threadfence();
            atomicExch(&g_flag, 1);       // release scan results
        }
        __syncthreads();
    } else {
        if (threadIdx.x == 0) {
            while (atomicAdd(&g_flag, 0) == 0) {}
        }
        __syncthreads();
        __threadfence();
    }

    // ---- fill phase (edge still in registers) ----
    if (valid) {
        int p = atomicAdd(&g_start[(int)dst], 1);
        if (p >= 0 && p < N_EDGES) g_src[p] = (int)src;
    }
    __syncthreads();
    if (threadIdx.x == 0) {
        __threadfence();
        if (atomicAdd(&g_ticket2, 1) == (int)gridDim.x - 1) {
            g_ticket2 = 0;
            g_flag = 0;                   // reset for next graph replay
        }
    }
}

// ---------------- 3) aggregate + normalize -> bf16 hi/lo, PLUS W hi/lo split ----------------
__global__ void __launch_bounds__(256) k_agg(const float* __restrict__ x,
                                             const float* __restrict__ noise,
                                             const float* __restrict__ W) {
    int b = blockIdx.x;
    if (b >= N_NODES) {                    // ---- W prep branch ----
        int k = b - N_NODES;
        int n = threadIdx.x;
        float v = (k < IN_F) ? W[(size_t)k * OUT_F + n] : 0.0f;
        __nv_bfloat16 hi = __float2bfloat16(v);
        __nv_bfloat16 lo = __float2bfloat16(v - __bfloat162float(hi));
        g_w_hi[(size_t)k * OUT_F + n] = hi;
        g_w_lo[(size_t)k * OUT_F + n] = lo;
        return;
    }

    int row = b;
    int t = threadIdx.x;
    size_t rb = (size_t)row * IN_F;

    float acc[6];
#pragma unroll
    for (int j = 0; j < 6; j++) {
        int f = t + j * 256;
        acc[j] = (f < IN_F) ? noise[rb + f] : 0.0f;
    }

    int e = g_start[row];                  // bucket end (after fill)
    int s = e - g_count[row];              // bucket start
    int ei = s;
    for (; ei + 3 < e; ei += 4) {          // 4-edge unroll for MLP
        const float* ip0 = x + (size_t)g_src[ei] * IN_F;
        const float* ip1 = x + (size_t)g_src[ei + 1] * IN_F;
        const float* ip2 = x + (size_t)g_src[ei + 2] * IN_F;
        const float* ip3 = x + (size_t)g_src[ei + 3] * IN_F;
#pragma unroll
        for (int j = 0; j < 6; j++) {
            int f = t + j * 256;
            if (f < IN_F) acc[j] += (ip0[f] + ip1[f]) + (ip2[f] + ip3[f]);
        }
    }
    for (; ei < e; ei++) {
        const float* ip = x + (size_t)g_src[ei] * IN_F;
#pragma unroll
        for (int j = 0; j < 6; j++) {
            int f = t + j * 256;
            if (f < IN_F) acc[j] += ip[f];
        }
    }

    float ss = 0.0f;
#pragma unroll
    for (int j = 0; j < 6; j++) ss += acc[j] * acc[j];

    __shared__ float red[256];
    red[t] = ss;
    __syncthreads();
    for (int o = 128; o > 0; o >>= 1) {
        if (t < o) red[t] += red[t + o];
        __syncthreads();
    }
    float rn = 1.0f / fmaxf(sqrtf(red[0]), 1e-12f);

    size_t rb2 = (size_t)row * K_PAD;
#pragma unroll
    for (int j = 0; j < 6; j++) {
        int f = t + j * 256;
        if (f < K_PAD) {
            float v = (f < IN_F) ? acc[j] * rn : 0.0f;
            __nv_bfloat16 hi = __float2bfloat16(v);
            __nv_bfloat16 lo = __float2bfloat16(v - __bfloat162float(hi));
            g_a_hi[rb2 + f] = hi;
            g_a_lo[rb2 + f] = lo;
        }
    }
}

// ---------------- 4) mma.sync bf16 split-precision GEMM ----------------
// CTA 64x64x32, 4 warps (warp = m16 x n64, one per SMSP), XOR-swizzled smem,
// 3-stage cp.async, 4 CTAs/SM
#define TILE_M   64
#define A_TILE   (TILE_M * 64)          // 4096 (rows of 64B, SW64)
#define B_TILE   (32 * 128)             // 4096 (rows of 128B, SW128)
#define ST_AHI   0
#define ST_ALO   A_TILE
#define ST_BHI   (2 * A_TILE)
#define ST_BLO   (2 * A_TILE + B_TILE)
#define STAGE_SZ (2 * A_TILE + 2 * B_TILE)   // 16384
#define NSTAGE   3
#define GEMM_SMEM (NSTAGE * STAGE_SZ)        // 49152

__global__ void __launch_bounds__(128, 4) k_gemm(const float* __restrict__ bias,
                                                 float* __restrict__ out) {
    extern __shared__ char smem[];
    uint32_t sb = smem_u32(smem);
    int tid = threadIdx.x;
    int lane = tid & 31;
    int wm = tid >> 5;                  // 0..3 -> M offset wm*16 (one warp per SMSP)
    int m0 = blockIdx.x * TILE_M;
    int n0 = blockIdx.y * 64;

    float acc[8][4];
#pragma unroll
    for (int j = 0; j < 8; j++)
#pragma unroll
        for (int q = 0; q < 4; q++) acc[j][q] = 0.0f;

    auto issue = [&](int c, int st) {
        uint32_t sg = sb + st * STAGE_SZ;
        int k0 = c * 32;
        // A hi/lo: 64 rows x 64B = 256 uint4, 2 per thread (SW64)
#pragma unroll
        for (int it = 0; it < 2; it++) {
            int idx = tid + it * 128;
            int r = idx >> 2, q = idx & 3;
            int row = m0 + r;
            uint32_t ok = (row < N_NODES) ? 16u : 0u;
            int rc = (row < N_NODES) ? row : (N_NODES - 1);
            size_t goff = (size_t)rc * K_PAD + k0 + q * 8;
            uint32_t sw = sw64((uint32_t)(r * 64 + q * 16));
            cp16(sg + ST_AHI + sw, (const char*)g_a_hi + goff * 2, ok);
            cp16(sg + ST_ALO + sw, (const char*)g_a_lo + goff * 2, ok);
        }
        // B hi/lo: 32 rows x 128B = 256 uint4, 2 per thread (SW128)
#pragma unroll
        for (int it = 0; it < 2; it++) {
            int idx = tid + it * 128;
            int r = idx >> 3, q = idx & 7;
            size_t goff = (size_t)(k0 + r) * OUT_F + n0 + q * 8;
            uint32_t sw = sw128((uint32_t)(r * 128 + q * 16));
            cp16(sg + ST_BHI + sw, (const char*)g_w_hi + goff * 2, 16u);
            cp16(sg + ST_BLO + sw, (const char*)g_w_lo + goff * 2, 16u);
        }
        cp_commit();
    };

    issue(0, 0);
    issue(1, 1);

    for (int c = 0; c < NCHUNK; c++) {
        int st = c % NSTAGE;
        if (c + 2 < NCHUNK) { issue(c + 2, (c + 2) % NSTAGE); cp_wait<2>(); }
        else if (c + 1 < NCHUNK) cp_wait<1>();
        else cp_wait<0>();
        __syncthreads();

        uint32_t sg = sb + st * STAGE_SZ;
#pragma unroll
        for (int kk = 0; kk < 2; kk++) {
            int kb = kk * 16;
            uint32_t ah[4], al[4];
            {
                int r = wm * 16 + (lane & 15);
                uint32_t off = (uint32_t)(r * 64 + kb * 2 + ((lane >> 4) << 4));
                uint32_t ra = sw64(off);
                ldsm_x4(ah, sg + ST_AHI + ra);
                ldsm_x4(al, sg + ST_ALO + ra);
            }
            uint32_t bh[4][4], bl[4][4];
#pragma unroll
            for (int nh = 0; nh < 4; nh++) {
                int r = kb + (lane & 15);
                uint32_t off = (uint32_t)(r * 128 + nh * 32 + ((lane >> 4) << 4));
                uint32_t rbb = sw128(off);
                ldsm_x4_t(bh[nh], sg + ST_BHI + rbb);
                ldsm_x4_t(bl[nh], sg + ST_BLO + rbb);
            }
#pragma unroll
            for (int ni = 0; ni < 8; ni++) {
                uint32_t b0h = bh[ni >> 1][(ni & 1) * 2];
                uint32_t b1h = bh[ni >> 1][(ni & 1) * 2 + 1];
                uint32_t b0l = bl[ni >> 1][(ni & 1) * 2];
                uint32_t b1l = bl[ni >> 1][(ni & 1) * 2 + 1];
                mma_bf16(acc[ni], ah, b0h, b1h);
                mma_bf16(acc[ni], al, b0h, b1h);
                mma_bf16(acc[ni], ah, b0l, b1l);
            }
        }
        __syncthreads();
    }

    // ---- epilogue: bias + store ----
    int r0 = m0 + wm * 16 + (lane >> 2);
#pragma unroll
    for (int ni = 0; ni < 8; ni++) {
        int col = n0 + ni * 8 + (lane & 3) * 2;
        float b0 = bias[col], b1 = bias[col + 1];
        if (r0 < N_NODES) {
            float2 v = make_float2(acc[ni][0] + b0, acc[ni][1] + b1);
            *(float2*)&out[(size_t)r0 * OUT_F + col] = v;
        }
        if (r0 + 8 < N_NODES) {
            float2 v = make_float2(acc[ni][2] + b0, acc[ni][3] + b1);
            *(float2*)&out[(size_t)(r0 + 8) * OUT_F + col] = v;
        }
    }
}

// ---------------- launch ----------------
extern "C" void kernel_launch(void* const* d_in, const int* in_sizes, int n_in,
                              void* d_out, int out_size) {
    const float* x     = nullptr;
    const void*  edges = nullptr;
    const float* W     = nullptr;
    const float* bias  = nullptr;
    const float* noise = nullptr;

    for (int i = 0; i < n_in; i++) {
        int sz = in_sizes[i];
        if (sz == N_EDGES * 2)            edges = d_in[i];
        else if (sz == IN_F * OUT_F)      W     = (const float*)d_in[i];
        else if (sz == OUT_F)             bias  = (const float*)d_in[i];
        else if (sz == N_NODES * IN_F) {
            if (!x) x = (const float*)d_in[i];
            else    noise = (const float*)d_in[i];
        }
    }
    float* out = (float*)d_out;
    (void)out_size;

    cudaFuncSetAttribute(k_gemm, cudaFuncAttributeMaxDynamicSharedMemorySize, GEMM_SMEM);

    k_init<<<(N_NODES + 255) / 256, 256>>>(edges);
    k_edges<<<EDGE_GRID, 1024>>>(edges);
    k_agg<<<N_NODES + K_PAD, 256>>>(x, noise, W);

    dim3 gg((N_NODES + TILE_M - 1) / TILE_M, OUT_F / 64);
    k_gemm<<<gg, 128, GEMM_SMEM>>>(bias, out);
}

// round 16
// speedup vs baseline: 1.1731x; 1.1731x over previous
#include <cuda_runtime.h>
#include <cuda_bf16.h>
#include <cuda_fp16.h>
#include <math.h>
#include <cstdint>

#define N_NODES 10000
#define N_EDGES 50000
#define IN_F    1433
#define OUT_F   256
#define K_PAD   1440              // 45 * 32
#define NCHUNK  45                // K chunks of 32

// ---------------- device scratch (no allocations allowed) ----------------
__device__ __half g_a_hi[(size_t)N_NODES * K_PAD];
__device__ __half g_a_lo[(size_t)N_NODES * K_PAD];
__device__ __half g_w[(size_t)K_PAD * OUT_F];   // [k][n], single fp16
__device__ int g_count[N_NODES];
__device__ int g_start[N_NODES + 1];   // after fill: bucket END per node
__device__ int g_src[N_EDGES];
__device__ int g_edges_is32;
__device__ int g_ticket1;              // zero-init; self-resetting
__device__ int g_ticket2;
__device__ int g_flag;

// ---------------- helpers ----------------
__device__ __forceinline__ uint32_t smem_u32(const void* p) {
    uint32_t a;
    asm("{ .reg .u64 t; cvta.to.shared.u64 t, %1; cvt.u32.u64 %0, t; }" : "=r"(a) : "l"(p));
    return a;
}
__device__ __forceinline__ void cp16(uint32_t dst, const void* src, uint32_t bytes) {
    asm volatile("cp.async.cg.shared.global [%0], [%1], 16, %2;"
                 :: "r"(dst), "l"(src), "r"(bytes) : "memory");
}
__device__ __forceinline__ void cp_commit() {
    asm volatile("cp.async.commit_group;" ::: "memory");
}
template <int N>
__device__ __forceinline__ void cp_wait() {
    asm volatile("cp.async.wait_group %0;" :: "n"(N) : "memory");
}
__device__ __forceinline__ void ldsm_x4(uint32_t (&r)[4], uint32_t addr) {
    asm volatile("ldmatrix.sync.aligned.m8n8.x4.shared.b16 {%0,%1,%2,%3}, [%4];"
                 : "=r"(r[0]), "=r"(r[1]), "=r"(r[2]), "=r"(r[3]) : "r"(addr));
}
__device__ __forceinline__ void ldsm_x4_t(uint32_t (&r)[4], uint32_t addr) {
    asm volatile("ldmatrix.sync.aligned.m8n8.x4.trans.shared.b16 {%0,%1,%2,%3}, [%4];"
                 : "=r"(r[0]), "=r"(r[1]), "=r"(r[2]), "=r"(r[3]) : "r"(addr));
}
__device__ __forceinline__ void mma_f16(float (&d)[4], const uint32_t (&a)[4],
                                        uint32_t b0, uint32_t b1) {
    asm volatile(
        "mma.sync.aligned.m16n8k16.row.col.f32.f16.f16.f32 "
        "{%0,%1,%2,%3}, {%4,%5,%6,%7}, {%8,%9}, {%0,%1,%2,%3};"
        : "+f"(d[0]), "+f"(d[1]), "+f"(d[2]), "+f"(d[3])
        : "r"(a[0]), "r"(a[1]), "r"(a[2]), "r"(a[3]), "r"(b0), "r"(b1));
}

// swizzles (byte offsets, tile-base-relative)
__device__ __forceinline__ uint32_t sw128(uint32_t off) { return off ^ ((off >> 3) & 0x70); }
__device__ __forceinline__ uint32_t sw64(uint32_t off)  { return off ^ ((off >> 3) & 0x30); }

// ---------------- 1) init: zero histogram + detect edge dtype ----------------
__global__ void __launch_bounds__(256) k_init(const void* __restrict__ edges) {
    int i = blockIdx.x * blockDim.x + threadIdx.x;
    if (i < N_NODES) g_count[i] = 0;
    if (blockIdx.x == 0 && threadIdx.x < 32) {
        const long long* e64 = (const long long*)edges;
        int lane = threadIdx.x;
        int bad = 0;
#pragma unroll
        for (int j = 0; j < 2; j++) {
            int p = lane * 2 + j;
            long long d = e64[2 * p], s = e64[2 * p + 1];
            if (d < 0 || d > N_NODES || s < 0 || s > N_NODES) bad = 1;
        }
        unsigned m = __ballot_sync(0xFFFFFFFFu, bad);
        if (lane == 0) g_edges_is32 = (m != 0) ? 1 : 0;
    }
}

__device__ __forceinline__ void load_edge(const void* edges, int e,
                                          long long& dst, long long& src) {
    if (g_edges_is32) {
        const int* p = (const int*)edges;
        dst = p[2 * e]; src = p[2 * e + 1];
    } else {
        const long long* p = (const long long*)edges;
        dst = p[2 * e]; src = p[2 * e + 1];
    }
}

// ---------------- 2) fused hist + scan + fill (49 co-resident blocks) ----------------
#define EDGE_GRID ((N_EDGES + 1023) / 1024)

__global__ void __launch_bounds__(1024) k_edges(const void* __restrict__ edges) {
    int e = blockIdx.x * 1024 + threadIdx.x;
    long long dst = -1, src = -1;
    bool valid = false;
    if (e < N_EDGES) {
        load_edge(edges, e, dst, src);
        valid = (src >= 0 && src < N_NODES && dst >= 0 && dst < N_NODES);
        if (valid) atomicAdd(&g_count[(int)dst], 1);
    }

    __shared__ int lastFlag;
    __syncthreads();
    if (threadIdx.x == 0) {
        __threadfence();
        lastFlag = (atomicAdd(&g_ticket1, 1) == (int)gridDim.x - 1);
    }
    __syncthreads();

    if (lastFlag) {
        __threadfence();
        // ---- exclusive scan over g_count (1024 threads, 10 bins each) ----
        __shared__ int wsum[32];
        const int CH = 10;
        int t = threadIdx.x;
        int lane = t & 31, w = t >> 5;
        int base = t * CH;
        int s = 0;
        int cnt[CH];
#pragma unroll
        for (int i = 0; i < CH; i++) {
            int idx = base + i;
            cnt[i] = (idx < N_NODES) ? g_count[idx] : 0;
            s += cnt[i];
        }
        int v = s;
#pragma unroll
        for (int off = 1; off < 32; off <<= 1) {
            int u = __shfl_up_sync(0xFFFFFFFFu, v, off);
            if (lane >= off) v += u;
        }
        if (lane == 31) wsum[w] = v;
        __syncthreads();
        if (w == 0) {
            int x = wsum[lane];
#pragma unroll
            for (int off = 1; off < 32; off <<= 1) {
                int u = __shfl_up_sync(0xFFFFFFFFu, x, off);
                if (lane >= off) x += u;
            }
            wsum[lane] = x;
        }
        __syncthreads();
        int run = ((w > 0) ? wsum[w - 1] : 0) + (v - s);
#pragma unroll
        for (int i = 0; i < CH; i++) {
            int idx = base + i;
            if (idx < N_NODES) {
                g_start[idx] = run;       // bucket start (fill turns it into end)
                run += cnt[i];
            }
        }
        if (t == 1023) g_start[N_NODES] = run;
        __syncthreads();
        if (t == 0) {
            g_ticket1 = 0;                // safe: all blocks already ticketed
            __threadfence();
            atomicExch(&g_flag, 1);       // release scan results
        }
        __syncthreads();
    } else {
        if (threadIdx.x == 0) {
            while (atomicAdd(&g_flag, 0) == 0) {}
        }
        __syncthreads();
        __threadfence();
    }

    // ---- fill phase (edge still in registers) ----
    if (valid) {
        int p = atomicAdd(&g_start[(int)dst], 1);
        if (p >= 0 && p < N_EDGES) g_src[p] = (int)src;
    }
    __syncthreads();
    if (threadIdx.x == 0) {
        __threadfence();
        if (atomicAdd(&g_ticket2, 1) == (int)gridDim.x - 1) {
            g_ticket2 = 0;
            g_flag = 0;                   // reset for next graph replay
        }
    }
}

// ---------------- 3) aggregate + normalize -> fp16 hi/lo, PLUS W fp16 ----------------
__global__ void __launch_bounds__(256) k_agg(const float* __restrict__ x,
                                             const float* __restrict__ noise,
                                             const float* __restrict__ W) {
    int b = blockIdx.x;
    if (b >= N_NODES) {                    // ---- W prep branch ----
        int k = b - N_NODES;
        int n = threadIdx.x;
        float v = (k < IN_F) ? W[(size_t)k * OUT_F + n] : 0.0f;
        g_w[(size_t)k * OUT_F + n] = __float2half_rn(v);
        return;
    }

    int row = b;
    int t = threadIdx.x;
    size_t rb = (size_t)row * IN_F;

    float acc[6];
#pragma unroll
    for (int j = 0; j < 6; j++) {
        int f = t + j * 256;
        acc[j] = (f < IN_F) ? noise[rb + f] : 0.0f;
    }

    int e = g_start[row];                  // bucket end (after fill)
    int s = e - g_count[row];              // bucket start
    int ei = s;
    for (; ei + 3 < e; ei += 4) {          // 4-edge unroll for MLP
        const float* ip0 = x + (size_t)g_src[ei] * IN_F;
        const float* ip1 = x + (size_t)g_src[ei + 1] * IN_F;
        const float* ip2 = x + (size_t)g_src[ei + 2] * IN_F;
        const float* ip3 = x + (size_t)g_src[ei + 3] * IN_F;
#pragma unroll
        for (int j = 0; j < 6; j++) {
            int f = t + j * 256;
            if (f < IN_F) acc[j] += (ip0[f] + ip1[f]) + (ip2[f] + ip3[f]);
        }
    }
    for (; ei < e; ei++) {
        const float* ip = x + (size_t)g_src[ei] * IN_F;
#pragma unroll
        for (int j = 0; j < 6; j++) {
            int f = t + j * 256;
            if (f < IN_F) acc[j] += ip[f];
        }
    }

    float ss = 0.0f;
#pragma unroll
    for (int j = 0; j < 6; j++) ss += acc[j] * acc[j];

    __shared__ float red[256];
    red[t] = ss;
    __syncthreads();
    for (int o = 128; o > 0; o >>= 1) {
        if (t < o) red[t] += red[t + o];
        __syncthreads();
    }
    float rn = 1.0f / fmaxf(sqrtf(red[0]), 1e-12f);

    size_t rb2 = (size_t)row * K_PAD;
#pragma unroll
    for (int j = 0; j < 6; j++) {
        int f = t + j * 256;
        if (f < K_PAD) {
            float v = (f < IN_F) ? acc[j] * rn : 0.0f;
            __half hi = __float2half_rn(v);
            __half lo = __float2half_rn(v - __half2float(hi));
            g_a_hi[rb2 + f] = hi;
            g_a_lo[rb2 + f] = lo;
        }
    }
}

// ---------------- 4) mma.sync fp16 2-term split GEMM ----------------
// CTA 64x64x32, 4 warps (warp = m16 x n64, one per SMSP), XOR-swizzled smem,
// 4-stage cp.async, 4 CTAs/SM
#define TILE_M   64
#define A_TILE   (TILE_M * 64)          // 4096 (rows of 64B, SW64)
#define B_TILE   (32 * 128)             // 4096 (rows of 128B, SW128)
#define ST_AHI   0
#define ST_ALO   A_TILE
#define ST_B     (2 * A_TILE)
#define STAGE_SZ (2 * A_TILE + B_TILE)       // 12288
#define NSTAGE   4
#define GEMM_SMEM (NSTAGE * STAGE_SZ)        // 49152

__global__ void __launch_bounds__(128, 4) k_gemm(const float* __restrict__ bias,
                                                 float* __restrict__ out) {
    extern __shared__ char smem[];
    uint32_t sb = smem_u32(smem);
    int tid = threadIdx.x;
    int lane = tid & 31;
    int wm = tid >> 5;                  // 0..3 -> M offset wm*16 (one warp per SMSP)
    int m0 = blockIdx.x * TILE_M;
    int n0 = blockIdx.y * 64;

    float acc[8][4];
#pragma unroll
    for (int j = 0; j < 8; j++)
#pragma unroll
        for (int q = 0; q < 4; q++) acc[j][q] = 0.0f;

    auto issue = [&](int c, int st) {
        uint32_t sg = sb + st * STAGE_SZ;
        int k0 = c * 32;
        // A hi/lo: 64 rows x 64B = 256 uint4, 2 per thread (SW64)
#pragma unroll
        for (int it = 0; it < 2; it++) {
            int idx = tid + it * 128;
            int r = idx >> 2, q = idx & 3;
            int row = m0 + r;
            uint32_t ok = (row < N_NODES) ? 16u : 0u;
            int rc = (row < N_NODES) ? row : (N_NODES - 1);
            size_t goff = (size_t)rc * K_PAD + k0 + q * 8;
            uint32_t sw = sw64((uint32_t)(r * 64 + q * 16));
            cp16(sg + ST_AHI + sw, (const char*)g_a_hi + goff * 2, ok);
            cp16(sg + ST_ALO + sw, (const char*)g_a_lo + goff * 2, ok);
        }
        // B: 32 rows x 128B = 256 uint4, 2 per thread (SW128)
#pragma unroll
        for (int it = 0; it < 2; it++) {
            int idx = tid + it * 128;
            int r = idx >> 3, q = idx & 7;
            size_t goff = (size_t)(k0 + r) * OUT_F + n0 + q * 8;
            uint32_t sw = sw128((uint32_t)(r * 128 + q * 16));
            cp16(sg + ST_B + sw, (const char*)g_w + goff * 2, 16u);
        }
        cp_commit();
    };

    issue(0, 0);
    issue(1, 1);
    issue(2, 2);

    for (int c = 0; c < NCHUNK; c++) {
        int st = c % NSTAGE;
        if (c + 3 < NCHUNK) { issue(c + 3, (c + 3) % NSTAGE); cp_wait<3>(); }
        else if (c + 2 < NCHUNK) cp_wait<2>();
        else if (c + 1 < NCHUNK) cp_wait<1>();
        else cp_wait<0>();
        __syncthreads();

        uint32_t sg = sb + st * STAGE_SZ;
#pragma unroll
        for (int kk = 0; kk < 2; kk++) {
            int kb = kk * 16;
            uint32_t ah[4], al[4];
            {
                int r = wm * 16 + (lane & 15);
                uint32_t off = (uint32_t)(r * 64 + kb * 2 + ((lane >> 4) << 4));
                uint32_t ra = sw64(off);
                ldsm_x4(ah, sg + ST_AHI + ra);
                ldsm_x4(al, sg + ST_ALO + ra);
            }
            uint32_t bf[4][4];
#pragma unroll
            for (int nh = 0; nh < 4; nh++) {
                int r = kb + (lane & 15);
                uint32_t off = (uint32_t)(r * 128 + nh * 32 + ((lane >> 4) << 4));
                uint32_t rbb = sw128(off);
                ldsm_x4_t(bf[nh], sg + ST_B + rbb);
            }
#pragma unroll
            for (int ni = 0; ni < 8; ni++) {
                uint32_t b0 = bf[ni >> 1][(ni & 1) * 2];
                uint32_t b1 = bf[ni >> 1][(ni & 1) * 2 + 1];
                mma_f16(acc[ni], ah, b0, b1);
                mma_f16(acc[ni], al, b0, b1);
            }
        }
        __syncthreads();
    }

    // ---- epilogue: bias + store ----
    int r0 = m0 + wm * 16 + (lane >> 2);
#pragma unroll
    for (int ni = 0; ni < 8; ni++) {
        int col = n0 + ni * 8 + (lane & 3) * 2;
        float b0 = bias[col], b1 = bias[col + 1];
        if (r0 < N_NODES) {
            float2 v = make_float2(acc[ni][0] + b0, acc[ni][1] + b1);
            *(float2*)&out[(size_t)r0 * OUT_F + col] = v;
        }
        if (r0 + 8 < N_NODES) {
            float2 v = make_float2(acc[ni][2] + b0, acc[ni][3] + b1);
            *(float2*)&out[(size_t)(r0 + 8) * OUT_F + col] = v;
        }
    }
}

// ---------------- launch ----------------
extern "C" void kernel_launch(void* const* d_in, const int* in_sizes, int n_in,
                              void* d_out, int out_size) {
    const float* x     = nullptr;
    const void*  edges = nullptr;
    const float* W     = nullptr;
    const float* bias  = nullptr;
    const float* noise = nullptr;

    for (int i = 0; i < n_in; i++) {
        int sz = in_sizes[i];
        if (sz == N_EDGES * 2)            edges = d_in[i];
        else if (sz == IN_F * OUT_F)      W     = (const float*)d_in[i];
        else if (sz == OUT_F)             bias  = (const float*)d_in[i];
        else if (sz == N_NODES * IN_F) {
            if (!x) x = (const float*)d_in[i];
            else    noise = (const float*)d_in[i];
        }
    }
    float* out = (float*)d_out;
    (void)out_size;

    cudaFuncSetAttribute(k_gemm, cudaFuncAttributeMaxDynamicSharedMemorySize, GEMM_SMEM);

    k_init<<<(N_NODES + 255) / 256, 256>>>(edges);
    k_edges<<<EDGE_GRID, 1024>>>(edges);
    k_agg<<<N_NODES + K_PAD, 256>>>(x, noise, W);

    dim3 gg((N_NODES + TILE_M - 1) / TILE_M, OUT_F / 64);
    k_gemm<<<gg, 128, GEMM_SMEM>>>(bias, out);
}